// round 8
// baseline (speedup 1.0000x reference)
#include <cuda_runtime.h>
#include <math.h>

#define BB   2
#define SS   2048
#define DD   2048
#define HQ   16
#define HKV  4
#define HD   128
#define KVD  512
#define MM   (BB*SS)
#define NT   (SS/64)

// Scratch (device globals)
__device__ float g_Q[(size_t)MM * DD];    // [token][d]  d-octets permuted, scaled
__device__ float g_K[(size_t)MM * KVD];   // [token][gd] d-octets permuted
__device__ float g_V[(size_t)MM * KVD];   // [token][gd] plain
__device__ float g_Vt[(size_t)BB * KVD * SS]; // [b*512+gd][s] s-octets permuted
__device__ float g_H[(size_t)MM * DD];    // tf32-rounded, k-octets permuted
__device__ float g_Wq[(size_t)DD * DD];   // [k][n] tf32-rounded
__device__ float g_Wk[(size_t)DD * KVD];
__device__ float g_Wv[(size_t)DD * KVD];

__device__ __forceinline__ unsigned f2tf(float x) {
    unsigned r;
    asm("cvt.rna.tf32.f32 %0, %1;" : "=r"(r) : "f"(x));
    return r;
}
__device__ __forceinline__ float f2tff(float x) { return __uint_as_float(f2tf(x)); }

__device__ __forceinline__ void mma_tf32(float c[4], const unsigned a[4], const unsigned b[2]) {
    asm volatile(
        "mma.sync.aligned.m16n8k8.row.col.f32.tf32.tf32.f32 "
        "{%0,%1,%2,%3},{%4,%5,%6,%7},{%8,%9},{%0,%1,%2,%3};"
        : "+f"(c[0]), "+f"(c[1]), "+f"(c[2]), "+f"(c[3])
        : "r"(a[0]), "r"(a[1]), "r"(a[2]), "r"(a[3]), "r"(b[0]), "r"(b[1]));
}

#define CP16(dst, src) \
    asm volatile("cp.async.cg.shared.global [%0], [%1], 16;" :: "r"(dst), "l"(src))
#define CPCOMMIT() asm volatile("cp.async.commit_group;")
#define CPWAIT(N)  asm volatile("cp.async.wait_group %0;" :: "n"(N))

#define MBAR_INIT(addr, cnt) \
    asm volatile("mbarrier.init.shared.b64 [%0], %1;" :: "r"(addr), "r"(cnt) : "memory")
#define MBAR_ARRIVE(addr) \
    asm volatile("mbarrier.arrive.shared.b64 _, [%0];" :: "r"(addr) : "memory")
#define CPASYNC_MBAR_ARRIVE(addr) \
    asm volatile("cp.async.mbarrier.arrive.noinc.shared.b64 [%0];" :: "r"(addr) : "memory")

#define MBAR_WAIT(addr, par) do { \
    unsigned _m = (addr), _p = (par), _d; \
    asm volatile("{\n\t.reg .pred p;\n\t" \
        "mbarrier.try_wait.parity.acquire.cta.shared::cta.b64 p, [%1], %2;\n\t" \
        "selp.b32 %0, 1, 0, p;\n\t}" : "=r"(_d) : "r"(_m), "r"(_p) : "memory"); \
    if (!_d) { \
        asm volatile("{\n\t.reg .pred P1;\n\t" \
            "WL%=:\n\t" \
            "mbarrier.try_wait.parity.acquire.cta.shared::cta.b64 P1, [%0], %1, 0x989680;\n\t" \
            "@P1 bra.uni WD%=;\n\t" \
            "bra.uni WL%=;\n\t" \
            "WD%=:\n\t}" :: "r"(_m), "r"(_p) : "memory"); \
    } \
} while (0)

// ---------------------------------------------------------------------------
// tf32-round (weights, natural order)
// ---------------------------------------------------------------------------
__global__ void cvt_tf32(float* __restrict__ dst, const float* __restrict__ src, int n4)
{
    int i = blockIdx.x * blockDim.x + threadIdx.x;
    int stride = gridDim.x * blockDim.x;
    for (; i < n4; i += stride) {
        float4 v = ((const float4*)src)[i];
        ((float4*)dst)[i] = make_float4(f2tff(v.x), f2tff(v.y), f2tff(v.z), f2tff(v.w));
    }
}

// ---------------------------------------------------------------------------
// tf32-round + octet permute [0,4,1,5,2,6,3,7]  (H / activations)
// ---------------------------------------------------------------------------
__global__ void cvt_tf32_perm(float* __restrict__ dst, const float* __restrict__ src, int n8)
{
    int i = blockIdx.x * blockDim.x + threadIdx.x;
    int stride = gridDim.x * blockDim.x;
    for (; i < n8; i += stride) {
        float4 a = ((const float4*)src)[2 * i];
        float4 b = ((const float4*)src)[2 * i + 1];
        ((float4*)dst)[2 * i] =
            make_float4(f2tff(a.x), f2tff(b.x), f2tff(a.y), f2tff(b.y));
        ((float4*)dst)[2 * i + 1] =
            make_float4(f2tff(a.z), f2tff(b.z), f2tff(a.w), f2tff(b.w));
    }
}

// ---------------------------------------------------------------------------
// Transpose V[b][s][gd] -> Vt[b*512+gd][s], s-octets permuted.
// ---------------------------------------------------------------------------
__global__ void transpose_v(float* __restrict__ Vt, const float* __restrict__ V)
{
    __shared__ float t[32][33];
    const int s0 = blockIdx.x * 32, gd0 = blockIdx.y * 32, b = blockIdx.z;
    #pragma unroll
    for (int i = 0; i < 4; i++) {
        int row = threadIdx.y + i * 8;
        t[row][threadIdx.x] =
            V[((size_t)b * SS + s0 + row) * KVD + gd0 + threadIdx.x];
    }
    __syncthreads();
    const int j = threadIdx.x;
    const int ssrc = (j & 24) + ((j & 1) ? 4 + ((j & 7) >> 1) : ((j & 7) >> 1));
    #pragma unroll
    for (int i = 0; i < 4; i++) {
        int gdl = threadIdx.y + i * 8;
        Vt[((size_t)b * KVD + gd0 + gdl) * SS + s0 + j] = t[ssrc][gdl];
    }
}

// ---------------------------------------------------------------------------
// tf32 GEMM + bias: Y = X@W + b. CTA tile 128x128x32, 8 warps (2m x 4n),
// 64x32 warp tiles, 2 CTAs/SM, cp.async double-buffered.
// ---------------------------------------------------------------------------
#define GA 5120
#define GB 4352
#define GBUF (GA + GB)
#define GEMM_SMEM_BYTES (GBUF * 2 * 4)

__device__ __forceinline__ void gemm_stage(
    unsigned sA, unsigned sB, const float* __restrict__ X, const float* __restrict__ W,
    int Kdim, int N, int bm, int bn, int k0, int tid)
{
    #pragma unroll
    for (int it = 0; it < 4; it++) {              // A: 128 x 32
        int f = tid + it * 256;
        int m  = f >> 3;
        int kq = (f & 7) * 4;
        CP16(sA + (m * 40 + kq) * 4, X + (size_t)(bm + m) * Kdim + k0 + kq);
    }
    #pragma unroll
    for (int it = 0; it < 4; it++) {              // B: 32 x 128
        int f = tid + it * 256;
        int kk = f >> 5;
        int nq = (f & 31) * 4;
        CP16(sB + (kk * 136 + nq) * 4, W + (size_t)(k0 + kk) * N + bn + nq);
    }
}

__global__ __launch_bounds__(256, 2) void gemm_tf32(
    const float* __restrict__ X,
    const float* __restrict__ W0, const float* __restrict__ b0, float* __restrict__ Y0,
    const float* __restrict__ W1, const float* __restrict__ b1, float* __restrict__ Y1,
    int N, int Kdim, float oscale, int perm0, int perm1)
{
    const float* __restrict__ W  = blockIdx.z ? W1 : W0;
    const float* __restrict__ bi = blockIdx.z ? b1 : b0;
    float*       __restrict__ Y  = blockIdx.z ? Y1 : Y0;
    const int permv = blockIdx.z ? perm1 : perm0;

    extern __shared__ unsigned smg[];
    const int tid  = threadIdx.x;
    const int lane = tid & 31;
    const int wid  = tid >> 5;
    const int wm   = wid & 1;
    const int wn   = wid >> 1;
    const int lr   = lane >> 2;
    const int lc   = lane & 3;
    const int bm = blockIdx.y * 128;
    const int bn = blockIdx.x * 128;

    unsigned sbase = (unsigned)__cvta_generic_to_shared(smg);

    float acc[4][4][4];
    #pragma unroll
    for (int i = 0; i < 4; i++)
        #pragma unroll
        for (int j = 0; j < 4; j++)
            #pragma unroll
            for (int k = 0; k < 4; k++) acc[i][j][k] = 0.f;

    const int nK = Kdim / 32;
    gemm_stage(sbase, sbase + GA * 4, X, W, Kdim, N, bm, bn, 0, tid);
    CPCOMMIT();

    for (int i = 0; i < nK; i++) {
        CPWAIT(0);
        __syncthreads();
        if (i + 1 < nK) {
            unsigned boff = ((i + 1) & 1) * GBUF * 4;
            gemm_stage(sbase + boff, sbase + boff + GA * 4,
                       X, W, Kdim, N, bm, bn, (i + 1) * 32, tid);
            CPCOMMIT();
        }
        const unsigned* As = smg + (i & 1) * GBUF;
        const unsigned* Bs = As + GA;

        #pragma unroll
        for (int s = 0; s < 4; s++) {
            const int c = s * 8 + lc;
            unsigned af[4][4], bf[4][2];
            #pragma unroll
            for (int mt = 0; mt < 4; mt++) {
                int r = wm * 64 + mt * 16 + lr;
                uint2 u1 = *(const uint2*)&As[r * 40 + s * 8 + 2 * lc];
                uint2 u2 = *(const uint2*)&As[(r + 8) * 40 + s * 8 + 2 * lc];
                af[mt][0] = u1.x; af[mt][1] = u2.x;
                af[mt][2] = u1.y; af[mt][3] = u2.y;
            }
            #pragma unroll
            for (int nt = 0; nt < 4; nt++) {
                int n = wn * 32 + nt * 8 + lr;
                bf[nt][0] = Bs[c * 136 + n];
                bf[nt][1] = Bs[(c + 4) * 136 + n];
            }
            #pragma unroll
            for (int mt = 0; mt < 4; mt++)
                #pragma unroll
                for (int nt = 0; nt < 4; nt++)
                    mma_tf32(acc[mt][nt], af[mt], bf[nt]);
        }
        __syncthreads();
    }

    const int p0 = (lc < 2) ? 4 * lc : 4 * lc - 7;
    const int p1 = (lc < 2) ? 4 * lc + 2 : 4 * lc - 5;
    #pragma unroll
    for (int mt = 0; mt < 4; mt++) {
        int r = bm + wm * 64 + mt * 16 + lr;
        #pragma unroll
        for (int nt = 0; nt < 4; nt++) {
            int base = bn + wn * 32 + nt * 8;
            float bv0 = bi[base + 2 * lc], bv1 = bi[base + 2 * lc + 1];
            float v00 = f2tff((acc[mt][nt][0] + bv0) * oscale);
            float v01 = f2tff((acc[mt][nt][1] + bv1) * oscale);
            float v10 = f2tff((acc[mt][nt][2] + bv0) * oscale);
            float v11 = f2tff((acc[mt][nt][3] + bv1) * oscale);
            if (permv) {
                Y[(size_t)r * N + base + p0] = v00;
                Y[(size_t)r * N + base + p1] = v01;
                Y[(size_t)(r + 8) * N + base + p0] = v10;
                Y[(size_t)(r + 8) * N + base + p1] = v11;
            } else {
                *(float2*)(Y + (size_t)r * N + base + 2 * lc) = make_float2(v00, v01);
                *(float2*)(Y + (size_t)(r + 8) * N + base + 2 * lc) = make_float2(v10, v11);
            }
        }
    }
}

// ---------------------------------------------------------------------------
// tf32 flash attention, software-pipelined: S(t+1) MMA issue overlaps
// softmax(t) latency chains. Q register-resident, K/Vt triple-buffered,
// no __syncthreads in main loop.
// ---------------------------------------------------------------------------
#define KSLOT 8704
#define VSLOT 9216
#define VBASE 26112
#define BARW  53760
#define ATTN_SMEM_BYTES (53776 * 4)

__device__ __forceinline__ void s_compute(
    float dst[8][4], const unsigned* __restrict__ Kst,
    const unsigned qa[16][4], int lr, int lc)
{
    #pragma unroll
    for (int nt = 0; nt < 8; nt++)
        #pragma unroll
        for (int k = 0; k < 4; k++) dst[nt][k] = 0.f;
    #pragma unroll
    for (int st = 0; st < 16; st++) {
        #pragma unroll
        for (int nt = 0; nt < 8; nt++) {
            uint2 bu = *(const uint2*)&Kst[(8 * nt + lr) * 136 + st * 8 + 2 * lc];
            unsigned bf[2] = { bu.x, bu.y };
            mma_tf32(dst[nt], qa[st], bf);
        }
    }
}

__global__ __launch_bounds__(256) void attn_tf32(
    const float* __restrict__ Q, const float* __restrict__ K,
    const float* __restrict__ Vt, float* __restrict__ O)
{
    extern __shared__ float sm[];

    const int tid  = threadIdx.x;
    const int lane = tid & 31;
    const int wid  = tid >> 5;
    const int lr = lane >> 2;
    const int lc = lane & 3;
    const int r0 = 16 * wid + lr;
    const int q0 = blockIdx.x * 128;
    const int h  = blockIdx.y;
    const int b  = blockIdx.z;
    const int g  = h & (HKV - 1);

    const float* Qb = Q  + (size_t)b * SS * DD  + (size_t)h * HD;
    const float* Kb = K  + (size_t)b * SS * KVD + (size_t)g * HD;
    const float* Vb = Vt + ((size_t)b * KVD + (size_t)g * HD) * SS;

    unsigned sbase = (unsigned)__cvta_generic_to_shared(sm);

    if (tid == 0) {
        #pragma unroll
        for (int s = 0; s < 3; s++) {
            MBAR_INIT(sbase + (BARW + 2 * s) * 4, 256);      // full[s]
            MBAR_INIT(sbase + (BARW + 6 + 2 * s) * 4, 256);  // empty[s]
        }
    }

    // --- Prologue: stage Q through K region, move to registers ---
    #pragma unroll
    for (int it = 0; it < 16; it++) {
        int f = tid + it * 256;
        int q  = f >> 5;
        int dq = (f & 31) * 4;
        CP16(sbase + (q * 136 + dq) * 4, Qb + (size_t)(q0 + q) * DD + dq);
    }
    CPCOMMIT();
    CPWAIT(0);
    __syncthreads();            // Q staged + barriers initialized

    unsigned qa[16][4];
    {
        const unsigned* Qs = (const unsigned*)sm;
        #pragma unroll
        for (int st = 0; st < 16; st++) {
            uint2 u1 = *(const uint2*)&Qs[r0 * 136 + st * 8 + 2 * lc];
            uint2 u2 = *(const uint2*)&Qs[(r0 + 8) * 136 + st * 8 + 2 * lc];
            qa[st][0] = u1.x; qa[st][1] = u2.x;
            qa[st][2] = u1.y; qa[st][3] = u2.y;
        }
    }
    __syncthreads();            // all Q reads done before K slot 0/1 fills

    // --- Fill slots 0 and 1 ---
    #pragma unroll
    for (int s = 0; s < 2; s++) {
        unsigned sKs = sbase + s * KSLOT * 4;
        unsigned sVs = sbase + (VBASE + s * VSLOT) * 4;
        #pragma unroll
        for (int it = 0; it < 8; it++) {
            int f = tid + it * 256;
            int key = f >> 5;
            int dq  = (f & 31) * 4;
            CP16(sKs + (key * 136 + dq) * 4,
                 Kb + (size_t)(s * 64 + key) * KVD + dq);
        }
        #pragma unroll
        for (int it = 0; it < 8; it++) {
            int f = tid + it * 256;
            int d  = f >> 4;
            int sq = (f & 15) * 4;
            CP16(sVs + (d * 72 + sq) * 4, Vb + (size_t)d * SS + s * 64 + sq);
        }
        CPASYNC_MBAR_ARRIVE(sbase + (BARW + 2 * s) * 4);
    }

    float o[16][4];
    #pragma unroll
    for (int dt = 0; dt < 16; dt++)
        #pragma unroll
        for (int k = 0; k < 4; k++) o[dt][k] = 0.f;
    float rm0 = -INFINITY, rm1 = -INFINITY, rl0 = 0.f, rl1 = 0.f;

    const int sAsrc = lr * 4 + (lc >> 1);
    const int sBsrc = sAsrc + 2;
    const bool oddc = (lc & 1);

    // S(0) into scur
    float scur[8][4], snxt[8][4];
    MBAR_WAIT(sbase + (BARW + 0) * 4, 0u);
    s_compute(scur, (const unsigned*)sm, qa, lr, lc);

    #pragma unroll 1
    for (int kt = 0; kt < NT; kt++) {
        // --- producer: fill slot (kt+2)%3 for tile kt+2 ---
        const int fs = kt + 2;
        if (fs < NT) {
            const int pslot = fs % 3;
            if (fs >= 3) MBAR_WAIT(sbase + (BARW + 6 + 2 * pslot) * 4,
                                   (unsigned)(((fs / 3) - 1) & 1));
            unsigned sKs = sbase + pslot * KSLOT * 4;
            unsigned sVs = sbase + (VBASE + pslot * VSLOT) * 4;
            #pragma unroll
            for (int it = 0; it < 8; it++) {
                int f = tid + it * 256;
                int key = f >> 5;
                int dq  = (f & 31) * 4;
                CP16(sKs + (key * 136 + dq) * 4,
                     Kb + (size_t)(fs * 64 + key) * KVD + dq);
            }
            #pragma unroll
            for (int it = 0; it < 8; it++) {
                int f = tid + it * 256;
                int d  = f >> 4;
                int sq = (f & 15) * 4;
                CP16(sVs + (d * 72 + sq) * 4, Vb + (size_t)d * SS + fs * 64 + sq);
            }
            CPASYNC_MBAR_ARRIVE(sbase + (BARW + 2 * pslot) * 4);
        }

        // ---- (1) softmax part 1: row max of scur (latency hidden by (2)) ----
        float m0 = scur[0][0], m1 = scur[0][2];
        #pragma unroll
        for (int nt = 0; nt < 8; nt++) {
            m0 = fmaxf(m0, fmaxf(scur[nt][0], scur[nt][1]));
            m1 = fmaxf(m1, fmaxf(scur[nt][2], scur[nt][3]));
        }
        m0 = fmaxf(m0, __shfl_xor_sync(0xffffffffu, m0, 1));
        m0 = fmaxf(m0, __shfl_xor_sync(0xffffffffu, m0, 2));
        m1 = fmaxf(m1, __shfl_xor_sync(0xffffffffu, m1, 1));
        m1 = fmaxf(m1, __shfl_xor_sync(0xffffffffu, m1, 2));

        // ---- (2) S(kt+1) MMA block into snxt ----
        if (kt + 1 < NT) {
            const int s1 = (kt + 1) % 3;
            MBAR_WAIT(sbase + (BARW + 2 * s1) * 4, (unsigned)(((kt + 1) / 3) & 1));
            s_compute(snxt, (const unsigned*)(sm + s1 * KSLOT), qa, lr, lc);
        }

        // ---- (3) softmax part 2: exp + pa + sums ----
        float mn0 = fmaxf(rm0, m0), mn1 = fmaxf(rm1, m1);
        float al0 = __expf(rm0 - mn0), al1 = __expf(rm1 - mn1);
        float sum0 = 0.f, sum1 = 0.f;
        unsigned pa[8][4];
        #pragma unroll
        for (int nt = 0; nt < 8; nt++) {
            float f0 = __expf(scur[nt][0] - mn0);
            float f1 = __expf(scur[nt][1] - mn0);
            float f2 = __expf(scur[nt][2] - mn1);
            float f3 = __expf(scur[nt][3] - mn1);
            sum0 += f0 + f1;
            sum1 += f2 + f3;
            unsigned t0 = f2tf(f0), t1 = f2tf(f1), t2 = f2tf(f2), t3 = f2tf(f3);
            unsigned e0 = __shfl_sync(0xffffffffu, t0, sAsrc);
            unsigned o0 = __shfl_sync(0xffffffffu, t1, sAsrc);
            unsigned e1 = __shfl_sync(0xffffffffu, t2, sAsrc);
            unsigned o1 = __shfl_sync(0xffffffffu, t3, sAsrc);
            unsigned e2 = __shfl_sync(0xffffffffu, t0, sBsrc);
            unsigned o2 = __shfl_sync(0xffffffffu, t1, sBsrc);
            unsigned e3 = __shfl_sync(0xffffffffu, t2, sBsrc);
            unsigned o3 = __shfl_sync(0xffffffffu, t3, sBsrc);
            pa[nt][0] = oddc ? o0 : e0;
            pa[nt][1] = oddc ? o1 : e1;
            pa[nt][2] = oddc ? o2 : e2;
            pa[nt][3] = oddc ? o3 : e3;
        }
        sum0 += __shfl_xor_sync(0xffffffffu, sum0, 1);
        sum0 += __shfl_xor_sync(0xffffffffu, sum0, 2);
        sum1 += __shfl_xor_sync(0xffffffffu, sum1, 1);
        sum1 += __shfl_xor_sync(0xffffffffu, sum1, 2);

        // ---- (4) rescale O, update stats ----
        rl0 = rl0 * al0 + sum0;  rm0 = mn0;
        rl1 = rl1 * al1 + sum1;  rm1 = mn1;
        #pragma unroll
        for (int dt = 0; dt < 16; dt++) {
            o[dt][0] *= al0;  o[dt][1] *= al0;
            o[dt][2] *= al1;  o[dt][3] *= al1;
        }

        // ---- (5) O += P V from slot kt%3 ----
        const int slot = kt % 3;
        const unsigned* Vts = (const unsigned*)(sm + VBASE + slot * VSLOT);
        #pragma unroll
        for (int nt = 0; nt < 8; nt++) {
            #pragma unroll
            for (int dt = 0; dt < 16; dt++) {
                uint2 vu = *(const uint2*)&Vts[(8 * dt + lr) * 72 + nt * 8 + 2 * lc];
                unsigned bf[2] = { vu.x, vu.y };
                mma_tf32(o[dt], pa[nt], bf);
            }
        }

        MBAR_ARRIVE(sbase + (BARW + 6 + 2 * slot) * 4);

        // rotate S accumulators
        #pragma unroll
        for (int nt = 0; nt < 8; nt++)
            #pragma unroll
            for (int k = 0; k < 4; k++) scur[nt][k] = snxt[nt][k];
    }

    // Epilogue
    float* Ob = O + (size_t)b * SS * DD + (size_t)h * HD;
    float inv0 = 1.f / rl0, inv1 = 1.f / rl1;
    #pragma unroll
    for (int dt = 0; dt < 16; dt++) {
        int cc = 8 * dt + 2 * lc;
        *(float2*)(Ob + (size_t)(q0 + r0) * DD + cc) =
            make_float2(o[dt][0] * inv0, o[dt][1] * inv0);
        *(float2*)(Ob + (size_t)(q0 + r0 + 8) * DD + cc) =
            make_float2(o[dt][2] * inv1, o[dt][3] * inv1);
    }
}

// ---------------------------------------------------------------------------
extern "C" void kernel_launch(void* const* d_in, const int* in_sizes, int n_in,
                              void* d_out, int out_size)
{
    (void)in_sizes; (void)n_in; (void)out_size;
    const float* H  = (const float*)d_in[0];
    const float* Wq = (const float*)d_in[1];
    const float* bq = (const float*)d_in[2];
    const float* Wk = (const float*)d_in[3];
    const float* bk = (const float*)d_in[4];
    const float* Wv = (const float*)d_in[5];
    const float* bv = (const float*)d_in[6];
    float* out = (float*)d_out;

    float *Qp, *Kp, *Vp, *Vtp, *Hp, *Wqp, *Wkp, *Wvp;
    cudaGetSymbolAddress((void**)&Qp,  g_Q);
    cudaGetSymbolAddress((void**)&Kp,  g_K);
    cudaGetSymbolAddress((void**)&Vp,  g_V);
    cudaGetSymbolAddress((void**)&Vtp, g_Vt);
    cudaGetSymbolAddress((void**)&Hp,  g_H);
    cudaGetSymbolAddress((void**)&Wqp, g_Wq);
    cudaGetSymbolAddress((void**)&Wkp, g_Wk);
    cudaGetSymbolAddress((void**)&Wvp, g_Wv);

    int nb = 148 * 8;
    cvt_tf32_perm<<<nb, 256>>>(Hp, H, (int)((size_t)MM * DD / 8));
    cvt_tf32<<<nb, 256>>>(Wqp, Wq, (int)((size_t)DD * DD / 4));
    cvt_tf32<<<nb, 256>>>(Wkp, Wk, (int)((size_t)DD * KVD / 4));
    cvt_tf32<<<nb, 256>>>(Wvp, Wv, (int)((size_t)DD * KVD / 4));

    const float scale = 0.08838834764831845f;  // 1/sqrt(128)
    cudaFuncSetAttribute(gemm_tf32,
                         cudaFuncAttributeMaxDynamicSharedMemorySize, GEMM_SMEM_BYTES);
    gemm_tf32<<<dim3(DD / 128, MM / 128, 1), 256, GEMM_SMEM_BYTES>>>(
        Hp, Wqp, bq, Qp, Wqp, bq, Qp, DD, DD, scale, 1, 1);
    gemm_tf32<<<dim3(KVD / 128, MM / 128, 2), 256, GEMM_SMEM_BYTES>>>(
        Hp, Wkp, bk, Kp, Wvp, bv, Vp, KVD, DD, 1.0f, 1, 0);

    transpose_v<<<dim3(SS / 32, KVD / 32, BB), dim3(32, 8)>>>(Vtp, Vp);

    cudaFuncSetAttribute(attn_tf32,
                         cudaFuncAttributeMaxDynamicSharedMemorySize, ATTN_SMEM_BYTES);
    attn_tf32<<<dim3(SS / 128, HQ, BB), 256, ATTN_SMEM_BYTES>>>(Qp, Kp, Vtp, out);
}

// round 9
// speedup vs baseline: 1.0480x; 1.0480x over previous
#include <cuda_runtime.h>
#include <math.h>

#define BB   2
#define SS   2048
#define DD   2048
#define HQ   16
#define HKV  4
#define HD   128
#define KVD  512
#define MM   (BB*SS)
#define NT   (SS/64)

// Scratch (device globals)
__device__ float g_Q[(size_t)MM * DD];    // [token][d]  d-octets permuted, scaled
__device__ float g_K[(size_t)MM * KVD];   // [token][gd] d-octets permuted
__device__ float g_V[(size_t)MM * KVD];   // [token][gd] plain
__device__ float g_Vt[(size_t)BB * KVD * SS]; // [b*512+gd][s] s-octets permuted
__device__ float g_H[(size_t)MM * DD];    // tf32-rounded, k-octets permuted
__device__ float g_Wq[(size_t)DD * DD];   // [k][n] tf32-rounded
__device__ float g_Wk[(size_t)DD * KVD];
__device__ float g_Wv[(size_t)DD * KVD];

__device__ __forceinline__ unsigned f2tf(float x) {
    unsigned r;
    asm("cvt.rna.tf32.f32 %0, %1;" : "=r"(r) : "f"(x));
    return r;
}
__device__ __forceinline__ float f2tff(float x) { return __uint_as_float(f2tf(x)); }

__device__ __forceinline__ void mma_tf32(float c[4], const unsigned a[4], const unsigned b[2]) {
    asm volatile(
        "mma.sync.aligned.m16n8k8.row.col.f32.tf32.tf32.f32 "
        "{%0,%1,%2,%3},{%4,%5,%6,%7},{%8,%9},{%0,%1,%2,%3};"
        : "+f"(c[0]), "+f"(c[1]), "+f"(c[2]), "+f"(c[3])
        : "r"(a[0]), "r"(a[1]), "r"(a[2]), "r"(a[3]), "r"(b[0]), "r"(b[1]));
}

#define CP16(dst, src) \
    asm volatile("cp.async.cg.shared.global [%0], [%1], 16;" :: "r"(dst), "l"(src))
#define CPCOMMIT() asm volatile("cp.async.commit_group;")
#define CPWAIT(N)  asm volatile("cp.async.wait_group %0;" :: "n"(N))

#define MBAR_INIT(addr, cnt) \
    asm volatile("mbarrier.init.shared.b64 [%0], %1;" :: "r"(addr), "r"(cnt) : "memory")
#define MBAR_ARRIVE(addr) \
    asm volatile("mbarrier.arrive.shared.b64 _, [%0];" :: "r"(addr) : "memory")
#define CPASYNC_MBAR_ARRIVE(addr) \
    asm volatile("cp.async.mbarrier.arrive.noinc.shared.b64 [%0];" :: "r"(addr) : "memory")

#define MBAR_WAIT(addr, par) do { \
    unsigned _m = (addr), _p = (par), _d; \
    asm volatile("{\n\t.reg .pred p;\n\t" \
        "mbarrier.try_wait.parity.acquire.cta.shared::cta.b64 p, [%1], %2;\n\t" \
        "selp.b32 %0, 1, 0, p;\n\t}" : "=r"(_d) : "r"(_m), "r"(_p) : "memory"); \
    if (!_d) { \
        asm volatile("{\n\t.reg .pred P1;\n\t" \
            "WL%=:\n\t" \
            "mbarrier.try_wait.parity.acquire.cta.shared::cta.b64 P1, [%0], %1, 0x989680;\n\t" \
            "@P1 bra.uni WD%=;\n\t" \
            "bra.uni WL%=;\n\t" \
            "WD%=:\n\t}" :: "r"(_m), "r"(_p) : "memory"); \
    } \
} while (0)

// ---------------------------------------------------------------------------
// tf32-round (weights, natural order)
// ---------------------------------------------------------------------------
__global__ void cvt_tf32(float* __restrict__ dst, const float* __restrict__ src, int n4)
{
    int i = blockIdx.x * blockDim.x + threadIdx.x;
    int stride = gridDim.x * blockDim.x;
    for (; i < n4; i += stride) {
        float4 v = ((const float4*)src)[i];
        ((float4*)dst)[i] = make_float4(f2tff(v.x), f2tff(v.y), f2tff(v.z), f2tff(v.w));
    }
}

// ---------------------------------------------------------------------------
// tf32-round + octet permute [0,4,1,5,2,6,3,7]  (H / activations)
// ---------------------------------------------------------------------------
__global__ void cvt_tf32_perm(float* __restrict__ dst, const float* __restrict__ src, int n8)
{
    int i = blockIdx.x * blockDim.x + threadIdx.x;
    int stride = gridDim.x * blockDim.x;
    for (; i < n8; i += stride) {
        float4 a = ((const float4*)src)[2 * i];
        float4 b = ((const float4*)src)[2 * i + 1];
        ((float4*)dst)[2 * i] =
            make_float4(f2tff(a.x), f2tff(b.x), f2tff(a.y), f2tff(b.y));
        ((float4*)dst)[2 * i + 1] =
            make_float4(f2tff(a.z), f2tff(b.z), f2tff(a.w), f2tff(b.w));
    }
}

// ---------------------------------------------------------------------------
// Transpose V[b][s][gd] -> Vt[b*512+gd][s], s-octets permuted.
// ---------------------------------------------------------------------------
__global__ void transpose_v(float* __restrict__ Vt, const float* __restrict__ V)
{
    __shared__ float t[32][33];
    const int s0 = blockIdx.x * 32, gd0 = blockIdx.y * 32, b = blockIdx.z;
    #pragma unroll
    for (int i = 0; i < 4; i++) {
        int row = threadIdx.y + i * 8;
        t[row][threadIdx.x] =
            V[((size_t)b * SS + s0 + row) * KVD + gd0 + threadIdx.x];
    }
    __syncthreads();
    const int j = threadIdx.x;
    const int ssrc = (j & 24) + ((j & 1) ? 4 + ((j & 7) >> 1) : ((j & 7) >> 1));
    #pragma unroll
    for (int i = 0; i < 4; i++) {
        int gdl = threadIdx.y + i * 8;
        Vt[((size_t)b * KVD + gd0 + gdl) * SS + s0 + j] = t[ssrc][gdl];
    }
}

// ---------------------------------------------------------------------------
// tf32 GEMM + bias: Y = X@W + b. CTA tile 128x256x32, 8 warps (2m x 4n),
// 64x64 warp tiles, cp.async double-buffered. X k-octets pre-permuted.
// (exact round-6 configuration — best passing)
// ---------------------------------------------------------------------------
#define GA 5120
#define GB 8448
#define GBUF (GA + GB)
#define GEMM_SMEM_BYTES (GBUF * 2 * 4)

__device__ __forceinline__ void gemm_stage(
    unsigned sA, unsigned sB, const float* __restrict__ X, const float* __restrict__ W,
    int Kdim, int N, int bm, int bn, int k0, int tid)
{
    #pragma unroll
    for (int it = 0; it < 4; it++) {              // A: 128 x 32
        int f = tid + it * 256;
        int m  = f >> 3;
        int kq = (f & 7) * 4;
        CP16(sA + (m * 40 + kq) * 4, X + (size_t)(bm + m) * Kdim + k0 + kq);
    }
    #pragma unroll
    for (int it = 0; it < 8; it++) {              // B: 32 x 256
        int f = tid + it * 256;
        int kk = f >> 6;
        int nq = (f & 63) * 4;
        CP16(sB + (kk * 264 + nq) * 4, W + (size_t)(k0 + kk) * N + bn + nq);
    }
}

__global__ __launch_bounds__(256) void gemm_tf32(
    const float* __restrict__ X,
    const float* __restrict__ W0, const float* __restrict__ b0, float* __restrict__ Y0,
    const float* __restrict__ W1, const float* __restrict__ b1, float* __restrict__ Y1,
    int N, int Kdim, float oscale, int perm0, int perm1)
{
    const float* __restrict__ W  = blockIdx.z ? W1 : W0;
    const float* __restrict__ bi = blockIdx.z ? b1 : b0;
    float*       __restrict__ Y  = blockIdx.z ? Y1 : Y0;
    const int permv = blockIdx.z ? perm1 : perm0;

    extern __shared__ unsigned smg[];
    const int tid  = threadIdx.x;
    const int lane = tid & 31;
    const int wid  = tid >> 5;
    const int wm   = wid >> 2;     // 0..1
    const int wn   = wid & 3;      // 0..3
    const int lr   = lane >> 2;
    const int lc   = lane & 3;
    const int bm = blockIdx.y * 128;
    const int bn = blockIdx.x * 256;

    unsigned sbase = (unsigned)__cvta_generic_to_shared(smg);

    float acc[4][8][4];
    #pragma unroll
    for (int i = 0; i < 4; i++)
        #pragma unroll
        for (int j = 0; j < 8; j++)
            #pragma unroll
            for (int k = 0; k < 4; k++) acc[i][j][k] = 0.f;

    const int nK = Kdim / 32;
    gemm_stage(sbase, sbase + GA * 4, X, W, Kdim, N, bm, bn, 0, tid);
    CPCOMMIT();

    for (int i = 0; i < nK; i++) {
        CPWAIT(0);
        __syncthreads();
        if (i + 1 < nK) {
            unsigned boff = ((i + 1) & 1) * GBUF * 4;
            gemm_stage(sbase + boff, sbase + boff + GA * 4,
                       X, W, Kdim, N, bm, bn, (i + 1) * 32, tid);
            CPCOMMIT();
        }
        const unsigned* As = smg + (i & 1) * GBUF;
        const unsigned* Bs = As + GA;

        #pragma unroll
        for (int s = 0; s < 4; s++) {
            const int c = s * 8 + lc;
            unsigned af[4][4], bf[8][2];
            #pragma unroll
            for (int mt = 0; mt < 4; mt++) {
                int r = wm * 64 + mt * 16 + lr;
                uint2 u1 = *(const uint2*)&As[r * 40 + s * 8 + 2 * lc];
                uint2 u2 = *(const uint2*)&As[(r + 8) * 40 + s * 8 + 2 * lc];
                af[mt][0] = u1.x; af[mt][1] = u2.x;
                af[mt][2] = u1.y; af[mt][3] = u2.y;
            }
            #pragma unroll
            for (int nt = 0; nt < 8; nt++) {
                int n = wn * 64 + nt * 8 + lr;
                bf[nt][0] = Bs[c * 264 + n];
                bf[nt][1] = Bs[(c + 4) * 264 + n];
            }
            #pragma unroll
            for (int mt = 0; mt < 4; mt++)
                #pragma unroll
                for (int nt = 0; nt < 8; nt++)
                    mma_tf32(acc[mt][nt], af[mt], bf[nt]);
        }
        __syncthreads();
    }

    const int p0 = (lc < 2) ? 4 * lc : 4 * lc - 7;
    const int p1 = (lc < 2) ? 4 * lc + 2 : 4 * lc - 5;
    #pragma unroll
    for (int mt = 0; mt < 4; mt++) {
        int r = bm + wm * 64 + mt * 16 + lr;
        #pragma unroll
        for (int nt = 0; nt < 8; nt++) {
            int base = bn + wn * 64 + nt * 8;
            float bv0 = bi[base + 2 * lc], bv1 = bi[base + 2 * lc + 1];
            float v00 = f2tff((acc[mt][nt][0] + bv0) * oscale);
            float v01 = f2tff((acc[mt][nt][1] + bv1) * oscale);
            float v10 = f2tff((acc[mt][nt][2] + bv0) * oscale);
            float v11 = f2tff((acc[mt][nt][3] + bv1) * oscale);
            if (permv) {
                Y[(size_t)r * N + base + p0] = v00;
                Y[(size_t)r * N + base + p1] = v01;
                Y[(size_t)(r + 8) * N + base + p0] = v10;
                Y[(size_t)(r + 8) * N + base + p1] = v11;
            } else {
                *(float2*)(Y + (size_t)r * N + base + 2 * lc) = make_float2(v00, v01);
                *(float2*)(Y + (size_t)(r + 8) * N + base + 2 * lc) = make_float2(v10, v11);
            }
        }
    }
}

// ---------------------------------------------------------------------------
// tf32 flash attention, mbarrier pipelined, Q register-resident.
// (exact round-6 configuration — best passing: 809 us)
// ---------------------------------------------------------------------------
#define KSLOT 8704
#define VSLOT 9216
#define VBASE 26112
#define BARW  53760
#define ATTN_SMEM_BYTES (53776 * 4)

__global__ __launch_bounds__(256) void attn_tf32(
    const float* __restrict__ Q, const float* __restrict__ K,
    const float* __restrict__ Vt, float* __restrict__ O)
{
    extern __shared__ float sm[];

    const int tid  = threadIdx.x;
    const int lane = tid & 31;
    const int wid  = tid >> 5;
    const int lr = lane >> 2;
    const int lc = lane & 3;
    const int r0 = 16 * wid + lr;
    const int q0 = blockIdx.x * 128;
    const int h  = blockIdx.y;
    const int b  = blockIdx.z;
    const int g  = h & (HKV - 1);

    const float* Qb = Q  + (size_t)b * SS * DD  + (size_t)h * HD;
    const float* Kb = K  + (size_t)b * SS * KVD + (size_t)g * HD;
    const float* Vb = Vt + ((size_t)b * KVD + (size_t)g * HD) * SS;

    unsigned sbase = (unsigned)__cvta_generic_to_shared(sm);

    if (tid == 0) {
        #pragma unroll
        for (int s = 0; s < 3; s++) {
            MBAR_INIT(sbase + (BARW + 2 * s) * 4, 256);      // full[s]
            MBAR_INIT(sbase + (BARW + 6 + 2 * s) * 4, 256);  // empty[s]
        }
    }

    // --- Prologue: stage Q through K region, move to registers ---
    #pragma unroll
    for (int it = 0; it < 16; it++) {
        int f = tid + it * 256;
        int q  = f >> 5;
        int dq = (f & 31) * 4;
        CP16(sbase + (q * 136 + dq) * 4, Qb + (size_t)(q0 + q) * DD + dq);
    }
    CPCOMMIT();
    CPWAIT(0);
    __syncthreads();            // Q staged + barriers initialized

    unsigned qa[16][4];
    {
        const unsigned* Qs = (const unsigned*)sm;
        #pragma unroll
        for (int st = 0; st < 16; st++) {
            uint2 u1 = *(const uint2*)&Qs[r0 * 136 + st * 8 + 2 * lc];
            uint2 u2 = *(const uint2*)&Qs[(r0 + 8) * 136 + st * 8 + 2 * lc];
            qa[st][0] = u1.x; qa[st][1] = u2.x;
            qa[st][2] = u1.y; qa[st][3] = u2.y;
        }
    }
    __syncthreads();            // all Q reads done before K slot 0/1 fills

    // --- Fill slots 0 and 1 ---
    #pragma unroll
    for (int s = 0; s < 2; s++) {
        unsigned sKs = sbase + s * KSLOT * 4;
        unsigned sVs = sbase + (VBASE + s * VSLOT) * 4;
        #pragma unroll
        for (int it = 0; it < 8; it++) {
            int f = tid + it * 256;
            int key = f >> 5;
            int dq  = (f & 31) * 4;
            CP16(sKs + (key * 136 + dq) * 4,
                 Kb + (size_t)(s * 64 + key) * KVD + dq);
        }
        #pragma unroll
        for (int it = 0; it < 8; it++) {
            int f = tid + it * 256;
            int d  = f >> 4;
            int sq = (f & 15) * 4;
            CP16(sVs + (d * 72 + sq) * 4, Vb + (size_t)d * SS + s * 64 + sq);
        }
        CPASYNC_MBAR_ARRIVE(sbase + (BARW + 2 * s) * 4);
    }

    float o[16][4];
    #pragma unroll
    for (int dt = 0; dt < 16; dt++)
        #pragma unroll
        for (int k = 0; k < 4; k++) o[dt][k] = 0.f;
    float rm0 = -INFINITY, rm1 = -INFINITY, rl0 = 0.f, rl1 = 0.f;

    const int sAsrc = lr * 4 + (lc >> 1);
    const int sBsrc = sAsrc + 2;
    const bool oddc = (lc & 1);

    #pragma unroll 1
    for (int kt = 0; kt < NT; kt++) {
        // --- producer: fill slot (kt+2)%3 for tile kt+2 ---
        const int fs = kt + 2;
        if (fs < NT) {
            const int slot = fs % 3;
            if (fs >= 3) MBAR_WAIT(sbase + (BARW + 6 + 2 * slot) * 4,
                                   (unsigned)(((fs / 3) - 1) & 1));
            unsigned sKs = sbase + slot * KSLOT * 4;
            unsigned sVs = sbase + (VBASE + slot * VSLOT) * 4;
            #pragma unroll
            for (int it = 0; it < 8; it++) {
                int f = tid + it * 256;
                int key = f >> 5;
                int dq  = (f & 31) * 4;
                CP16(sKs + (key * 136 + dq) * 4,
                     Kb + (size_t)(fs * 64 + key) * KVD + dq);
            }
            #pragma unroll
            for (int it = 0; it < 8; it++) {
                int f = tid + it * 256;
                int d  = f >> 4;
                int sq = (f & 15) * 4;
                CP16(sVs + (d * 72 + sq) * 4, Vb + (size_t)d * SS + fs * 64 + sq);
            }
            CPASYNC_MBAR_ARRIVE(sbase + (BARW + 2 * slot) * 4);
        }

        // --- consumer: wait slot kt%3 full ---
        const int slot = kt % 3;
        MBAR_WAIT(sbase + (BARW + 2 * slot) * 4, (unsigned)((kt / 3) & 1));
        const unsigned* Kst = (const unsigned*)(sm + slot * KSLOT);
        const unsigned* Vts = (const unsigned*)(sm + VBASE + slot * VSLOT);

        // ---- S = Q K^T ----
        float sacc[8][4];
        #pragma unroll
        for (int nt = 0; nt < 8; nt++)
            #pragma unroll
            for (int k = 0; k < 4; k++) sacc[nt][k] = 0.f;

        #pragma unroll
        for (int st = 0; st < 16; st++) {
            #pragma unroll
            for (int nt = 0; nt < 8; nt++) {
                uint2 bu = *(const uint2*)&Kst[(8 * nt + lr) * 136 + st * 8 + 2 * lc];
                unsigned bf[2] = { bu.x, bu.y };
                mma_tf32(sacc[nt], qa[st], bf);
            }
        }

        // ---- warp-private online softmax; P -> a-frags via shuffles ----
        float m0 = sacc[0][0], m1 = sacc[0][2];
        #pragma unroll
        for (int nt = 0; nt < 8; nt++) {
            m0 = fmaxf(m0, fmaxf(sacc[nt][0], sacc[nt][1]));
            m1 = fmaxf(m1, fmaxf(sacc[nt][2], sacc[nt][3]));
        }
        m0 = fmaxf(m0, __shfl_xor_sync(0xffffffffu, m0, 1));
        m0 = fmaxf(m0, __shfl_xor_sync(0xffffffffu, m0, 2));
        m1 = fmaxf(m1, __shfl_xor_sync(0xffffffffu, m1, 1));
        m1 = fmaxf(m1, __shfl_xor_sync(0xffffffffu, m1, 2));
        float mn0 = fmaxf(rm0, m0), mn1 = fmaxf(rm1, m1);
        float al0 = __expf(rm0 - mn0), al1 = __expf(rm1 - mn1);
        float sum0 = 0.f, sum1 = 0.f;
        unsigned pa[8][4];
        #pragma unroll
        for (int nt = 0; nt < 8; nt++) {
            float f0 = __expf(sacc[nt][0] - mn0);
            float f1 = __expf(sacc[nt][1] - mn0);
            float f2 = __expf(sacc[nt][2] - mn1);
            float f3 = __expf(sacc[nt][3] - mn1);
            sum0 += f0 + f1;
            sum1 += f2 + f3;
            unsigned t0 = f2tf(f0), t1 = f2tf(f1), t2 = f2tf(f2), t3 = f2tf(f3);
            unsigned e0 = __shfl_sync(0xffffffffu, t0, sAsrc);
            unsigned o0 = __shfl_sync(0xffffffffu, t1, sAsrc);
            unsigned e1 = __shfl_sync(0xffffffffu, t2, sAsrc);
            unsigned o1 = __shfl_sync(0xffffffffu, t3, sAsrc);
            unsigned e2 = __shfl_sync(0xffffffffu, t0, sBsrc);
            unsigned o2 = __shfl_sync(0xffffffffu, t1, sBsrc);
            unsigned e3 = __shfl_sync(0xffffffffu, t2, sBsrc);
            unsigned o3 = __shfl_sync(0xffffffffu, t3, sBsrc);
            pa[nt][0] = oddc ? o0 : e0;
            pa[nt][1] = oddc ? o1 : e1;
            pa[nt][2] = oddc ? o2 : e2;
            pa[nt][3] = oddc ? o3 : e3;
        }
        sum0 += __shfl_xor_sync(0xffffffffu, sum0, 1);
        sum0 += __shfl_xor_sync(0xffffffffu, sum0, 2);
        sum1 += __shfl_xor_sync(0xffffffffu, sum1, 1);
        sum1 += __shfl_xor_sync(0xffffffffu, sum1, 2);
        rl0 = rl0 * al0 + sum0;  rm0 = mn0;
        rl1 = rl1 * al1 + sum1;  rm1 = mn1;
        #pragma unroll
        for (int dt = 0; dt < 16; dt++) {
            o[dt][0] *= al0;  o[dt][1] *= al0;
            o[dt][2] *= al1;  o[dt][3] *= al1;
        }

        // ---- O += P V ----
        #pragma unroll
        for (int nt = 0; nt < 8; nt++) {
            #pragma unroll
            for (int dt = 0; dt < 16; dt++) {
                uint2 vu = *(const uint2*)&Vts[(8 * dt + lr) * 72 + nt * 8 + 2 * lc];
                unsigned bf[2] = { vu.x, vu.y };
                mma_tf32(o[dt], pa[nt], bf);
            }
        }

        // release slot
        MBAR_ARRIVE(sbase + (BARW + 6 + 2 * slot) * 4);
    }

    // Epilogue
    float* Ob = O + (size_t)b * SS * DD + (size_t)h * HD;
    float inv0 = 1.f / rl0, inv1 = 1.f / rl1;
    #pragma unroll
    for (int dt = 0; dt < 16; dt++) {
        int cc = 8 * dt + 2 * lc;
        *(float2*)(Ob + (size_t)(q0 + r0) * DD + cc) =
            make_float2(o[dt][0] * inv0, o[dt][1] * inv0);
        *(float2*)(Ob + (size_t)(q0 + r0 + 8) * DD + cc) =
            make_float2(o[dt][2] * inv1, o[dt][3] * inv1);
    }
}

// ---------------------------------------------------------------------------
// Launch: fork/join across two streams so the independent projection chains
// overlap.  Stream 0: H/Wq cvt -> Q-gemm -> (join) -> attention.
// Stream s2: Wk/Wv cvt -> (wait H) -> KV-gemm -> transpose_v -> (join).
// Events are DisableTiming; this is the standard graph-capture fork pattern.
// ---------------------------------------------------------------------------
extern "C" void kernel_launch(void* const* d_in, const int* in_sizes, int n_in,
                              void* d_out, int out_size)
{
    (void)in_sizes; (void)n_in; (void)out_size;
    const float* H  = (const float*)d_in[0];
    const float* Wq = (const float*)d_in[1];
    const float* bq = (const float*)d_in[2];
    const float* Wk = (const float*)d_in[3];
    const float* bk = (const float*)d_in[4];
    const float* Wv = (const float*)d_in[5];
    const float* bv = (const float*)d_in[6];
    float* out = (float*)d_out;

    static cudaStream_t s2 = 0;
    static cudaEvent_t eFork = 0, eH = 0, eKV = 0;
    if (s2 == 0) {
        cudaStreamCreateWithFlags(&s2, cudaStreamNonBlocking);
        cudaEventCreateWithFlags(&eFork, cudaEventDisableTiming);
        cudaEventCreateWithFlags(&eH,    cudaEventDisableTiming);
        cudaEventCreateWithFlags(&eKV,   cudaEventDisableTiming);
    }

    float *Qp, *Kp, *Vp, *Vtp, *Hp, *Wqp, *Wkp, *Wvp;
    cudaGetSymbolAddress((void**)&Qp,  g_Q);
    cudaGetSymbolAddress((void**)&Kp,  g_K);
    cudaGetSymbolAddress((void**)&Vp,  g_V);
    cudaGetSymbolAddress((void**)&Vtp, g_Vt);
    cudaGetSymbolAddress((void**)&Hp,  g_H);
    cudaGetSymbolAddress((void**)&Wqp, g_Wq);
    cudaGetSymbolAddress((void**)&Wkp, g_Wk);
    cudaGetSymbolAddress((void**)&Wvp, g_Wv);

    cudaFuncSetAttribute(gemm_tf32,
                         cudaFuncAttributeMaxDynamicSharedMemorySize, GEMM_SMEM_BYTES);
    cudaFuncSetAttribute(attn_tf32,
                         cudaFuncAttributeMaxDynamicSharedMemorySize, ATTN_SMEM_BYTES);

    const float scale = 0.08838834764831845f;  // 1/sqrt(128)
    const int nb = 148 * 8;

    // Fork s2 off the capture/main stream.
    cudaEventRecord(eFork, 0);
    cudaStreamWaitEvent(s2, eFork, 0);

    // Stream 0: H (needed by both gemms) + Wq cvt.
    cvt_tf32_perm<<<nb, 256>>>(Hp, H, (int)((size_t)MM * DD / 8));
    cvt_tf32<<<nb, 256>>>(Wqp, Wq, (int)((size_t)DD * DD / 4));
    cudaEventRecord(eH, 0);

    // Stream s2: Wk/Wv cvt (independent of H).
    cvt_tf32<<<nb, 256, 0, s2>>>(Wkp, Wk, (int)((size_t)DD * KVD / 4));
    cvt_tf32<<<nb, 256, 0, s2>>>(Wvp, Wv, (int)((size_t)DD * KVD / 4));
    cudaStreamWaitEvent(s2, eH, 0);   // KV-gemm also reads H

    // Stream 0: Q projection (N=2048, scale folded, output octet-permuted).
    gemm_tf32<<<dim3(DD / 256, MM / 128, 1), 256, GEMM_SMEM_BYTES>>>(
        Hp, Wqp, bq, Qp, Wqp, bq, Qp, DD, DD, scale, 1, 1);

    // Stream s2: K (permuted) + V (plain) projections, then V transpose.
    gemm_tf32<<<dim3(KVD / 256, MM / 128, 2), 256, GEMM_SMEM_BYTES, s2>>>(
        Hp, Wkp, bk, Kp, Wvp, bv, Vp, KVD, DD, 1.0f, 1, 0);
    transpose_v<<<dim3(SS / 32, KVD / 32, BB), dim3(32, 8), 0, s2>>>(Vtp, Vp);
    cudaEventRecord(eKV, s2);

    // Join: attention needs Q (stream 0) and K/Vt (s2).
    cudaStreamWaitEvent(0, eKV, 0);
    attn_tf32<<<dim3(SS / 128, HQ, BB), 256, ATTN_SMEM_BYTES>>>(Qp, Kp, Vtp, out);
}